// round 3
// baseline (speedup 1.0000x reference)
#include <cuda_runtime.h>
#include <cuda_bf16.h>
#include <mma.h>
#include <cstddef>
#include <cstdint>

using namespace nvcuda;

#define BB    32
#define TKK   1024
#define HH    512
#define EE    256
#define VOCAB 50257
#define M_ENC (BB * TKK)   // 32768

// ---------------- scratch (__device__ globals) ------------------------------
__device__ float g_xinT[(HH + EE) * BB];
__device__ float g_hT[HH * BB];
__device__ float g_xT[EE * BB];
__device__ float g_giT[3 * HH * BB];
__device__ float g_ghT[3 * HH * BB];
__device__ float g_hnewT[HH * BB];
__device__ float g_dec[BB * HH];
__device__ float g_scores[BB * TKK];
__device__ float g_cpart[BB * 16 * HH];
__device__ float g_concatT[2 * HH * BB];
__device__ float g_out1[BB * HH];
__device__ float g_logits[(size_t)BB * VOCAB];
__device__ __nv_bfloat16 g_whb[HH * HH];      // bf16 Wh, [n][k]

__device__ __forceinline__ float sigmoidf_(float x) { return 1.f / (1.f + __expf(-x)); }
__device__ __forceinline__ float tanh_fast(float x) {
    float r; asm("tanh.approx.f32 %0, %1;" : "=f"(r) : "f"(x)); return r;
}
__device__ __forceinline__ void cp16(uint32_t dst, const void* src) {
    asm volatile("cp.async.cg.shared.global [%0], [%1], 16;" :: "r"(dst), "l"(src));
}
__device__ __forceinline__ void cp_commit() { asm volatile("cp.async.commit_group;"); }
template<int N> __device__ __forceinline__ void cp_wait() {
    asm volatile("cp.async.wait_group %0;" :: "n"(N));
}

// ---------------- convert Wh -> bf16 ----------------------------------------
__global__ void k_convert_wh(const float* __restrict__ Wh) {
    int i = blockIdx.x * blockDim.x + threadIdx.x;   // over 131072 pairs
    float2 v = *(const float2*)(Wh + i * 2);
    *(__nv_bfloat162*)(g_whb + i * 2) = __floats2bfloat162_rn(v.x, v.y);
}

// ---------------- build xinT [768][32] and hT [512][32] ---------------------
__global__ void k_build_front(const int* __restrict__ yt,
                              const float* __restrict__ c_t_1,
                              const float* __restrict__ s_t_1,
                              const float* __restrict__ emb) {
    int b = blockIdx.x;
    int yid = yt[b];
    for (int k = threadIdx.x; k < HH; k += blockDim.x) {
        g_xinT[k * BB + b] = c_t_1[b * HH + k];
        g_hT[k * BB + b]   = s_t_1[b * HH + k];
    }
    for (int k = threadIdx.x; k < EE; k += blockDim.x)
        g_xinT[(HH + k) * BB + b] = emb[(size_t)yid * EE + k];
}

// ---------------- transposed small GEMM -------------------------------------
// warp = one n, lane = batch. AT [K][32] read coalesced from L2; W read once.
// yT[n*32+b] and/or yR[b*N+n].
__global__ __launch_bounds__(256) void k_bdots_t(float* __restrict__ yT,
                                                 float* __restrict__ yR,
                                                 const float* __restrict__ AT,
                                                 const float* __restrict__ W,
                                                 const float* __restrict__ bias,
                                                 int N, int K) {
    int gwarp = (blockIdx.x * blockDim.x + threadIdx.x) >> 5;
    int lane = threadIdx.x & 31;
    int n = gwarp;
    const float4* w4 = (const float4*)(W + (size_t)n * K);
    const float* a = AT + lane;
    float a0 = 0.f, a1 = 0.f, a2 = 0.f, a3 = 0.f;
    int K4 = K >> 2;
    for (int k4 = 0; k4 < K4; k4++) {
        float4 w = w4[k4];
        const float* ak = a + (k4 << 7);
        a0 += w.x * ak[0];
        a1 += w.y * ak[32];
        a2 += w.z * ak[64];
        a3 += w.w * ak[96];
    }
    float r = (a0 + a1) + (a2 + a3) + bias[n];
    if (yT) yT[n * BB + lane] = r;
    if (yR) yR[(size_t)lane * N + n] = r;
}

// ---------------- GRU: warp per j, lane per b -------------------------------
__global__ void k_gru(float* __restrict__ out_st) {
    int j = (blockIdx.x * blockDim.x + threadIdx.x) >> 5;
    int b = threadIdx.x & 31;
    float ir = g_giT[j * BB + b],            hr = g_ghT[j * BB + b];
    float iz = g_giT[(HH + j) * BB + b],     hz = g_ghT[(HH + j) * BB + b];
    float in_ = g_giT[(2 * HH + j) * BB + b], hn = g_ghT[(2 * HH + j) * BB + b];
    float r = sigmoidf_(ir + hr);
    float z = sigmoidf_(iz + hz);
    float nn = tanhf(in_ + r * hn);
    float h = g_hT[j * BB + b];
    float hv = (1.f - z) * nn + z * h;
    g_hnewT[j * BB + b] = hv;
    g_concatT[j * BB + b] = hv;
    out_st[b * HH + j] = hv;
}

// ---------------- fused: scores = v . tanh(enc@Wh^T + dec) ------------------
// block 512 thr, tile M=64 x N=512, K pipelined in chunks of 32 (cp.async).
#define FA_SMEM (4096 + 133120)
__global__ __launch_bounds__(512) void k_fused_attn(const float* __restrict__ enc,
                                                    const float* __restrict__ vw) {
    extern __shared__ char smraw[];
    float* sdec = (float*)smraw;                         // [512]
    float* sv   = sdec + 512;                            // [512]
    __nv_bfloat16* As = (__nv_bfloat16*)(smraw + 4096);  // [2][64][40]
    __nv_bfloat16* Bs = (__nv_bfloat16*)(smraw + 14336); // [3][512][40]
    float* stage = (float*)(smraw + 4096);               // [64][520] (epilogue)

    int tid = threadIdx.x, warp = tid >> 5, lane = tid & 31;
    int bt = blockIdx.x;
    int b  = bt >> 4;
    size_t m0 = (size_t)bt * 64;

    sdec[tid] = g_dec[b * HH + tid];
    sv[tid]   = vw[tid];

    int wm = warp >> 3, wn = warp & 7;
    wmma::fragment<wmma::accumulator, 16, 16, 16, float> acc[2][4];
#pragma unroll
    for (int i = 0; i < 2; i++)
#pragma unroll
        for (int j = 0; j < 4; j++) wmma::fill_fragment(acc[i][j], 0.f);

    uint32_t bs_base = (uint32_t)__cvta_generic_to_shared(Bs);
    int arow = tid >> 3, aq = tid & 7;

    // prologue: B chunk 0 + A chunk 0
    {
        uint32_t dst = bs_base + tid * 80;
        const char* src = (const char*)(g_whb + tid * HH);
#pragma unroll
        for (int j = 0; j < 4; j++) cp16(dst + j * 16, src + j * 16);
        cp_commit();
    }
    float4 areg = *(const float4*)(enc + (m0 + arow) * HH + aq * 4);

    const int NIT = HH / 32;   // 16
    for (int it = 0; it < NIT; it++) {
        int cur2 = it & 1, cur3 = it - (it / 3) * 3;
        // issue next B chunk
        if (it < NIT - 1) {
            int n3 = (it + 1) - ((it + 1) / 3) * 3;
            uint32_t dst = bs_base + n3 * 40960 + tid * 80;
            const char* src = (const char*)(g_whb + tid * HH + (it + 1) * 32);
#pragma unroll
            for (int j = 0; j < 4; j++) cp16(dst + j * 16, src + j * 16);
            cp_commit();
        }
        // store A(it) regs -> As[cur2]
        __nv_bfloat16* ad = As + cur2 * (64 * 40) + arow * 40 + aq * 4;
        *(__nv_bfloat162*)ad       = __floats2bfloat162_rn(areg.x, areg.y);
        *(__nv_bfloat162*)(ad + 2) = __floats2bfloat162_rn(areg.z, areg.w);
        // preload A(it+1)
        if (it < NIT - 1)
            areg = *(const float4*)(enc + (m0 + arow) * HH + (it + 1) * 32 + aq * 4);
        if (it < NIT - 1) cp_wait<1>(); else cp_wait<0>();
        __syncthreads();
        // mma on chunk it (k=32 -> 2 steps of 16)
        const __nv_bfloat16* ab = As + cur2 * (64 * 40);
        const __nv_bfloat16* bb = Bs + cur3 * (512 * 40);
#pragma unroll
        for (int kk = 0; kk < 32; kk += 16) {
            wmma::fragment<wmma::matrix_a, 16, 16, 16, __nv_bfloat16, wmma::row_major> af[2];
#pragma unroll
            for (int i = 0; i < 2; i++)
                wmma::load_matrix_sync(af[i], ab + (wm * 32 + i * 16) * 40 + kk, 40);
#pragma unroll
            for (int j = 0; j < 4; j++) {
                wmma::fragment<wmma::matrix_b, 16, 16, 16, __nv_bfloat16, wmma::col_major> bf;
                wmma::load_matrix_sync(bf, bb + (wn * 64 + j * 16) * 40 + kk, 40);
                wmma::mma_sync(acc[0][j], af[0], bf, acc[0][j]);
                wmma::mma_sync(acc[1][j], af[1], bf, acc[1][j]);
            }
        }
    }
    __syncthreads();   // loop smem -> stage reuse
#pragma unroll
    for (int i = 0; i < 2; i++)
#pragma unroll
        for (int j = 0; j < 4; j++)
            wmma::store_matrix_sync(stage + (wm * 32 + i * 16) * 520 + wn * 64 + j * 16,
                                    acc[i][j], 520, wmma::mem_row_major);
    __syncthreads();
#pragma unroll
    for (int rr = 0; rr < 4; rr++) {
        int r = warp * 4 + rr;
        const float* sr = stage + r * 520;
        float a = 0.f;
#pragma unroll
        for (int itn = 0; itn < 16; itn++) {
            int n = lane + itn * 32;
            a += sv[n] * tanh_fast(sr[n] + sdec[n]);
        }
#pragma unroll
        for (int o = 16; o; o >>= 1) a += __shfl_down_sync(0xffffffffu, a, o);
        if (lane == 0) g_scores[bt * 64 + r] = a;
    }
}

// ---------------- softmax over TK per b -------------------------------------
__global__ void k_attn(float* __restrict__ out_attn) {
    __shared__ float red[32];
    int b = blockIdx.x, t = threadIdx.x;   // 1024 threads
    float s = g_scores[b * TKK + t];
    float m = s;
#pragma unroll
    for (int o = 16; o; o >>= 1) m = fmaxf(m, __shfl_xor_sync(0xffffffffu, m, o));
    if ((t & 31) == 0) red[t >> 5] = m;
    __syncthreads();
    if (t < 32) {
        float v = red[t];
#pragma unroll
        for (int o = 16; o; o >>= 1) v = fmaxf(v, __shfl_xor_sync(0xffffffffu, v, o));
        if (t == 0) red[0] = v;
    }
    __syncthreads();
    float mx = red[0];
    __syncthreads();
    float e = __expf(s - mx);
    float sm = e;
#pragma unroll
    for (int o = 16; o; o >>= 1) sm += __shfl_xor_sync(0xffffffffu, sm, o);
    if ((t & 31) == 0) red[t >> 5] = sm;
    __syncthreads();
    if (t < 32) {
        float v = red[t];
#pragma unroll
        for (int o = 16; o; o >>= 1) v += __shfl_xor_sync(0xffffffffu, v, o);
        if (t == 0) red[0] = v;
    }
    __syncthreads();
    out_attn[b * TKK + t] = e * (1.f / red[0]);
}

// ---------------- c_t partials ----------------------------------------------
__global__ void k_ct_part(const float* __restrict__ enc, const float* __restrict__ attn) {
    __shared__ float sa[64];
    int c = blockIdx.x, b = blockIdx.y, h = threadIdx.x;   // 512 threads
    if (h < 64) sa[h] = attn[b * TKK + c * 64 + h];
    __syncthreads();
    const float* e = enc + ((size_t)b * TKK + c * 64) * HH + h;
    float acc = 0.f;
#pragma unroll 8
    for (int t = 0; t < 64; t++) acc += sa[t] * e[(size_t)t * HH];
    g_cpart[((size_t)b * 16 + c) * HH + h] = acc;
}

__global__ void k_ct_fin(float* __restrict__ out_ct) {
    int b = blockIdx.x, h = threadIdx.x;   // 512
    float acc = 0.f;
#pragma unroll
    for (int c = 0; c < 16; c++) acc += g_cpart[((size_t)b * 16 + c) * HH + h];
    out_ct[b * HH + h] = acc;
    g_concatT[(HH + h) * BB + b] = acc;
}

// ---------------- logits via wmma, double buffered --------------------------
#define LG_SMEM (33280 + 20480)
__global__ __launch_bounds__(256) void k_logits_mma(const float* __restrict__ W,
                                                    const float* __restrict__ bias) {
    extern __shared__ char smraw[];
    __nv_bfloat16* As2 = (__nv_bfloat16*)smraw;                // [32][520]
    __nv_bfloat16* Ws  = (__nv_bfloat16*)(smraw + 33280);      // [2][128][40]
    float* stage = (float*)(smraw + 33280);                    // [32][136]

    int tid = threadIdx.x, warp = tid >> 5;
    int n0 = blockIdx.x * 128;
    for (int idx = tid; idx < BB * HH; idx += 256) {
        int r = idx >> 9, k = idx & 511;
        As2[r * 520 + k] = __float2bfloat16(g_out1[idx]);
    }

    wmma::fragment<wmma::accumulator, 16, 16, 16, float> acc[2];
    wmma::fill_fragment(acc[0], 0.f);
    wmma::fill_fragment(acc[1], 0.f);

    int lrow = tid >> 3, lq = tid & 7;
    float4 wreg[4];
#pragma unroll
    for (int p = 0; p < 4; p++) {
        int n = n0 + p * 32 + lrow;
        wreg[p] = (n < VOCAB) ? *(const float4*)(W + (size_t)n * HH + lq * 4)
                              : make_float4(0.f, 0.f, 0.f, 0.f);
    }
    for (int it = 0; it < 16; it++) {
        int cur = it & 1;
        __nv_bfloat16* wd = Ws + cur * (128 * 40);
#pragma unroll
        for (int p = 0; p < 4; p++) {
            __nv_bfloat16* d = wd + (p * 32 + lrow) * 40 + lq * 4;
            *(__nv_bfloat162*)d       = __floats2bfloat162_rn(wreg[p].x, wreg[p].y);
            *(__nv_bfloat162*)(d + 2) = __floats2bfloat162_rn(wreg[p].z, wreg[p].w);
        }
        if (it < 15) {
#pragma unroll
            for (int p = 0; p < 4; p++) {
                int n = n0 + p * 32 + lrow;
                wreg[p] = (n < VOCAB)
                    ? *(const float4*)(W + (size_t)n * HH + (it + 1) * 32 + lq * 4)
                    : make_float4(0.f, 0.f, 0.f, 0.f);
            }
        }
        __syncthreads();
#pragma unroll
        for (int kk = 0; kk < 32; kk += 16) {
            wmma::fragment<wmma::matrix_b, 16, 16, 16, __nv_bfloat16, wmma::col_major> bf;
            wmma::load_matrix_sync(bf, wd + (warp * 16) * 40 + kk, 40);
#pragma unroll
            for (int i = 0; i < 2; i++) {
                wmma::fragment<wmma::matrix_a, 16, 16, 16, __nv_bfloat16, wmma::row_major> af;
                wmma::load_matrix_sync(af, As2 + (i * 16) * 520 + it * 32 + kk, 520);
                wmma::mma_sync(acc[i], af, bf, acc[i]);
            }
        }
    }
    __syncthreads();
#pragma unroll
    for (int i = 0; i < 2; i++)
        wmma::store_matrix_sync(stage + (i * 16) * 136 + warp * 16, acc[i], 136,
                                wmma::mem_row_major);
    __syncthreads();
    for (int idx = tid; idx < 32 * 128; idx += 256) {
        int r = idx >> 7, c = idx & 127;
        int n = n0 + c;
        if (n < VOCAB)
            g_logits[(size_t)r * VOCAB + n] = stage[r * 136 + c] + bias[n];
    }
}

// ---------------- softmax over V per b --------------------------------------
__global__ void k_softmaxV(float* __restrict__ out_fd) {
    __shared__ float red[32];
    int b = blockIdx.x, tid = threadIdx.x;     // 512 threads
    const float* lg = g_logits + (size_t)b * VOCAB;
    float* dst = out_fd + (size_t)b * VOCAB;

    float m = -1e30f;
    for (int n = tid; n < VOCAB; n += 512) m = fmaxf(m, lg[n]);
#pragma unroll
    for (int o = 16; o; o >>= 1) m = fmaxf(m, __shfl_xor_sync(0xffffffffu, m, o));
    if ((tid & 31) == 0) red[tid >> 5] = m;
    __syncthreads();
    if (tid < 32) {
        float v = (tid < 16) ? red[tid] : -1e30f;
#pragma unroll
        for (int o = 16; o; o >>= 1) v = fmaxf(v, __shfl_xor_sync(0xffffffffu, v, o));
        if (tid == 0) red[0] = v;
    }
    __syncthreads();
    float mx = red[0];
    __syncthreads();
    float s = 0.f;
    for (int n = tid; n < VOCAB; n += 512) {
        float e = __expf(lg[n] - mx);
        dst[n] = e;
        s += e;
    }
#pragma unroll
    for (int o = 16; o; o >>= 1) s += __shfl_xor_sync(0xffffffffu, s, o);
    if ((tid & 31) == 0) red[tid >> 5] = s;
    __syncthreads();
    if (tid < 32) {
        float v = (tid < 16) ? red[tid] : 0.f;
#pragma unroll
        for (int o = 16; o; o >>= 1) v += __shfl_xor_sync(0xffffffffu, v, o);
        if (tid == 0) red[0] = v;
    }
    __syncthreads();
    float inv = 1.f / red[0];
    for (int n = tid; n < VOCAB; n += 512) dst[n] *= inv;
}

// ---------------- launcher ---------------------------------------------------
extern "C" void kernel_launch(void* const* d_in, const int* in_sizes, int n_in,
                              void* d_out, int out_size) {
    const int*   y      = (const int*)d_in[0];
    const float* s_t_1  = (const float*)d_in[2];
    const float* enc    = (const float*)d_in[3];
    const float* c_t_1  = (const float*)d_in[4];
    const float* cov    = (const float*)d_in[5];
    const float* emb    = (const float*)d_in[7];
    const float* xc_w   = (const float*)d_in[8];
    const float* xc_b   = (const float*)d_in[9];
    const float* Wh_w   = (const float*)d_in[10];
    const float* w_ih   = (const float*)d_in[11];
    const float* w_hh   = (const float*)d_in[12];
    const float* b_ih   = (const float*)d_in[13];
    const float* b_hh   = (const float*)d_in[14];
    const float* dp_w   = (const float*)d_in[15];
    const float* dp_b   = (const float*)d_in[16];
    const float* v_w    = (const float*)d_in[17];
    const float* out1_w = (const float*)d_in[18];
    const float* out1_b = (const float*)d_in[19];
    const float* out2_w = (const float*)d_in[20];
    const float* out2_b = (const float*)d_in[21];

    float* out      = (float*)d_out;
    float* out_fd   = out;
    float* out_st   = out_fd + (size_t)BB * VOCAB;
    float* out_ct   = out_st + BB * HH;
    float* out_attn = out_ct + BB * HH;
    float* out_cov  = out_attn + BB * TKK;

    float *p_xinT, *p_hT, *p_xT, *p_giT, *p_ghT, *p_hnewT, *p_dec, *p_concatT, *p_out1;
    cudaGetSymbolAddress((void**)&p_xinT,    g_xinT);
    cudaGetSymbolAddress((void**)&p_hT,      g_hT);
    cudaGetSymbolAddress((void**)&p_xT,      g_xT);
    cudaGetSymbolAddress((void**)&p_giT,     g_giT);
    cudaGetSymbolAddress((void**)&p_ghT,     g_ghT);
    cudaGetSymbolAddress((void**)&p_hnewT,   g_hnewT);
    cudaGetSymbolAddress((void**)&p_dec,     g_dec);
    cudaGetSymbolAddress((void**)&p_concatT, g_concatT);
    cudaGetSymbolAddress((void**)&p_out1,    g_out1);

    cudaFuncSetAttribute(k_fused_attn, cudaFuncAttributeMaxDynamicSharedMemorySize, FA_SMEM);
    cudaFuncSetAttribute(k_logits_mma, cudaFuncAttributeMaxDynamicSharedMemorySize, LG_SMEM);

    k_convert_wh<<<512, 256>>>(Wh_w);
    k_build_front<<<BB, 256>>>(y, c_t_1, s_t_1, emb);
    // x = xin @ xc_w^T
    k_bdots_t<<<EE / 8, 256>>>(p_xT, nullptr, p_xinT, xc_w, xc_b, EE, HH + EE);
    k_bdots_t<<<3 * HH / 8, 256>>>(p_ghT, nullptr, p_hT, w_hh, b_hh, 3 * HH, HH);
    k_bdots_t<<<3 * HH / 8, 256>>>(p_giT, nullptr, p_xT, w_ih, b_ih, 3 * HH, EE);
    k_gru<<<HH / 8, 256>>>(out_st);
    k_bdots_t<<<HH / 8, 256>>>(nullptr, p_dec, p_hnewT, dp_w, dp_b, HH, HH);
    // fused attention scores
    k_fused_attn<<<M_ENC / 64, 512, FA_SMEM>>>(enc, v_w);
    k_attn<<<BB, 1024>>>(out_attn);
    k_ct_part<<<dim3(16, BB), 512>>>(enc, out_attn);
    k_ct_fin<<<BB, 512>>>(out_ct);
    // vocab projection
    k_bdots_t<<<HH / 8, 256>>>(nullptr, p_out1, p_concatT, out1_w, out1_b, HH, 2 * HH);
    k_logits_mma<<<(VOCAB + 127) / 128, 256, LG_SMEM>>>(out2_w, out2_b);
    k_softmaxV<<<BB, 512>>>(out_fd);
    cudaMemcpyAsync(out_cov, cov, (size_t)BB * TKK * sizeof(float),
                    cudaMemcpyDeviceToDevice, 0);
}

// round 4
// speedup vs baseline: 1.4271x; 1.4271x over previous
#include <cuda_runtime.h>
#include <cuda_bf16.h>
#include <mma.h>
#include <cstddef>
#include <cstdint>

using namespace nvcuda;

#define BB    32
#define TKK   1024
#define HH    512
#define EE    256
#define VOCAB 50257
#define M_ENC (BB * TKK)   // 32768

// ---------------- scratch (__device__ globals) ------------------------------
__device__ float g_xinT[(HH + EE) * BB];
__device__ float g_hT[HH * BB];
__device__ float g_xT[EE * BB];
__device__ float g_giT[3 * HH * BB];
__device__ float g_ghT[3 * HH * BB];
__device__ float g_hnewT[HH * BB];
__device__ float g_dec[BB * HH];
__device__ float g_scores[BB * TKK];
__device__ float g_cpart[BB * 16 * HH];
__device__ float g_concatT[2 * HH * BB];
__device__ float g_out1[BB * HH];
__device__ float g_logits[(size_t)BB * VOCAB];
__device__ __nv_bfloat16 g_whb[HH * HH];      // bf16 Wh, [n][k]

__device__ __forceinline__ float sigmoidf_(float x) { return 1.f / (1.f + __expf(-x)); }
__device__ __forceinline__ float tanh_fast(float x) {
    float r; asm("tanh.approx.f32 %0, %1;" : "=f"(r) : "f"(x)); return r;
}
__device__ __forceinline__ void cp16(uint32_t dst, const void* src) {
    asm volatile("cp.async.cg.shared.global [%0], [%1], 16;" :: "r"(dst), "l"(src));
}
__device__ __forceinline__ void cp_commit() { asm volatile("cp.async.commit_group;"); }
template<int N> __device__ __forceinline__ void cp_wait() {
    asm volatile("cp.async.wait_group %0;" :: "n"(N));
}

// ---------------- init outputs with bias (all 5 small GEMMs at once) --------
__global__ void k_init_bias(const float* __restrict__ xc_b,
                            const float* __restrict__ b_ih,
                            const float* __restrict__ b_hh,
                            const float* __restrict__ dp_b,
                            const float* __restrict__ out1_b) {
    int idx = blockIdx.x * 256 + threadIdx.x;      // 4352*32 = 139264
    if (idx >= 4352 * 32) return;
    int n = idx >> 5, b = idx & 31;
    if (n < EE)        { g_xT[n * 32 + b] = xc_b[n];  return; }  n -= EE;
    if (n < 3 * HH)    { g_giT[n * 32 + b] = b_ih[n]; return; }  n -= 3 * HH;
    if (n < 3 * HH)    { g_ghT[n * 32 + b] = b_hh[n]; return; }  n -= 3 * HH;
    if (n < HH)        { g_dec[b * HH + n] = dp_b[n]; return; }  n -= HH;
    g_out1[b * HH + n] = out1_b[n];
}

// ---------------- convert Wh -> bf16 ----------------------------------------
__global__ void k_convert_wh(const float* __restrict__ Wh) {
    int i = blockIdx.x * blockDim.x + threadIdx.x;   // over 131072 pairs
    float2 v = *(const float2*)(Wh + i * 2);
    *(__nv_bfloat162*)(g_whb + i * 2) = __floats2bfloat162_rn(v.x, v.y);
}

// ---------------- build xinT [768][32] and hT [512][32] ---------------------
__global__ void k_build_front(const int* __restrict__ yt,
                              const float* __restrict__ c_t_1,
                              const float* __restrict__ s_t_1,
                              const float* __restrict__ emb) {
    int b = blockIdx.x;
    int yid = yt[b];
    for (int k = threadIdx.x; k < HH; k += blockDim.x) {
        g_xinT[k * BB + b] = c_t_1[b * HH + k];
        g_hT[k * BB + b]   = s_t_1[b * HH + k];
    }
    for (int k = threadIdx.x; k < EE; k += blockDim.x)
        g_xinT[(HH + k) * BB + b] = emb[(size_t)yid * EE + k];
}

// ---------------- split-K small GEMM ----------------------------------------
// grid (N/8, KS). warp = one n, lane = batch. Partial over K/KS, atomicAdd out.
// Output must be pre-initialized with bias (k_init_bias).
__global__ __launch_bounds__(256) void k_bsplit(float* __restrict__ yT,
                                                float* __restrict__ yR,
                                                const float* __restrict__ AT,
                                                const float* __restrict__ W,
                                                int N, int K) {
    int warp = threadIdx.x >> 5, lane = threadIdx.x & 31;
    int n = blockIdx.x * 8 + warp;
    int kchunk = K >> 2;                    // KS = 4
    int k0 = blockIdx.y * kchunk;
    const float4* w4 = (const float4*)(W + (size_t)n * K + k0);
    const float* a = AT + k0 * 32 + lane;
    float a0 = 0.f, a1 = 0.f, a2 = 0.f, a3 = 0.f;
    int iters = kchunk >> 2;
#pragma unroll 8
    for (int i = 0; i < iters; i++) {
        float4 w = w4[i];
        const float* ak = a + (i << 7);
        a0 += w.x * ak[0];
        a1 += w.y * ak[32];
        a2 += w.z * ak[64];
        a3 += w.w * ak[96];
    }
    float r = (a0 + a1) + (a2 + a3);
    if (yT) atomicAdd(&yT[n * 32 + lane], r);
    if (yR) atomicAdd(&yR[(size_t)lane * N + n], r);
}

// ---------------- GRU: warp per j, lane per b -------------------------------
__global__ void k_gru(float* __restrict__ out_st) {
    int j = (blockIdx.x * blockDim.x + threadIdx.x) >> 5;
    int b = threadIdx.x & 31;
    float ir = g_giT[j * BB + b],            hr = g_ghT[j * BB + b];
    float iz = g_giT[(HH + j) * BB + b],     hz = g_ghT[(HH + j) * BB + b];
    float in_ = g_giT[(2 * HH + j) * BB + b], hn = g_ghT[(2 * HH + j) * BB + b];
    float r = sigmoidf_(ir + hr);
    float z = sigmoidf_(iz + hz);
    float nn = tanhf(in_ + r * hn);
    float h = g_hT[j * BB + b];
    float hv = (1.f - z) * nn + z * h;
    g_hnewT[j * BB + b] = hv;
    g_concatT[j * BB + b] = hv;
    out_st[b * HH + j] = hv;
}

// ---------------- fused: scores = v . tanh(enc@Wh^T + dec) ------------------
// block 512 thr, tile M=64 x N=512, K pipelined in chunks of 32 (cp.async).
#define FA_SMEM (4096 + 133120)
__global__ __launch_bounds__(512) void k_fused_attn(const float* __restrict__ enc,
                                                    const float* __restrict__ vw) {
    extern __shared__ char smraw[];
    float* sdec = (float*)smraw;                         // [512]
    float* sv   = sdec + 512;                            // [512]
    __nv_bfloat16* As = (__nv_bfloat16*)(smraw + 4096);  // [2][64][40]
    __nv_bfloat16* Bs = (__nv_bfloat16*)(smraw + 14336); // [3][512][40]
    float* stage = (float*)(smraw + 4096);               // [64][520] (epilogue)

    int tid = threadIdx.x, warp = tid >> 5, lane = tid & 31;
    int bt = blockIdx.x;
    int b  = bt >> 4;
    size_t m0 = (size_t)bt * 64;

    sdec[tid] = g_dec[b * HH + tid];
    sv[tid]   = vw[tid];

    int wm = warp >> 3, wn = warp & 7;
    wmma::fragment<wmma::accumulator, 16, 16, 16, float> acc[2][4];
#pragma unroll
    for (int i = 0; i < 2; i++)
#pragma unroll
        for (int j = 0; j < 4; j++) wmma::fill_fragment(acc[i][j], 0.f);

    uint32_t bs_base = (uint32_t)__cvta_generic_to_shared(Bs);
    int arow = tid >> 3, aq = tid & 7;

    {
        uint32_t dst = bs_base + tid * 80;
        const char* src = (const char*)(g_whb + tid * HH);
#pragma unroll
        for (int j = 0; j < 4; j++) cp16(dst + j * 16, src + j * 16);
        cp_commit();
    }
    float4 areg = *(const float4*)(enc + (m0 + arow) * HH + aq * 4);

    const int NIT = HH / 32;   // 16
    for (int it = 0; it < NIT; it++) {
        int cur2 = it & 1, cur3 = it - (it / 3) * 3;
        if (it < NIT - 1) {
            int n3 = (it + 1) - ((it + 1) / 3) * 3;
            uint32_t dst = bs_base + n3 * 40960 + tid * 80;
            const char* src = (const char*)(g_whb + tid * HH + (it + 1) * 32);
#pragma unroll
            for (int j = 0; j < 4; j++) cp16(dst + j * 16, src + j * 16);
            cp_commit();
        }
        __nv_bfloat16* ad = As + cur2 * (64 * 40) + arow * 40 + aq * 4;
        *(__nv_bfloat162*)ad       = __floats2bfloat162_rn(areg.x, areg.y);
        *(__nv_bfloat162*)(ad + 2) = __floats2bfloat162_rn(areg.z, areg.w);
        if (it < NIT - 1)
            areg = *(const float4*)(enc + (m0 + arow) * HH + (it + 1) * 32 + aq * 4);
        if (it < NIT - 1) cp_wait<1>(); else cp_wait<0>();
        __syncthreads();
        const __nv_bfloat16* ab = As + cur2 * (64 * 40);
        const __nv_bfloat16* bb = Bs + cur3 * (512 * 40);
#pragma unroll
        for (int kk = 0; kk < 32; kk += 16) {
            wmma::fragment<wmma::matrix_a, 16, 16, 16, __nv_bfloat16, wmma::row_major> af[2];
#pragma unroll
            for (int i = 0; i < 2; i++)
                wmma::load_matrix_sync(af[i], ab + (wm * 32 + i * 16) * 40 + kk, 40);
#pragma unroll
            for (int j = 0; j < 4; j++) {
                wmma::fragment<wmma::matrix_b, 16, 16, 16, __nv_bfloat16, wmma::col_major> bf;
                wmma::load_matrix_sync(bf, bb + (wn * 64 + j * 16) * 40 + kk, 40);
                wmma::mma_sync(acc[0][j], af[0], bf, acc[0][j]);
                wmma::mma_sync(acc[1][j], af[1], bf, acc[1][j]);
            }
        }
    }
    __syncthreads();
#pragma unroll
    for (int i = 0; i < 2; i++)
#pragma unroll
        for (int j = 0; j < 4; j++)
            wmma::store_matrix_sync(stage + (wm * 32 + i * 16) * 520 + wn * 64 + j * 16,
                                    acc[i][j], 520, wmma::mem_row_major);
    __syncthreads();
#pragma unroll
    for (int rr = 0; rr < 4; rr++) {
        int r = warp * 4 + rr;
        const float* sr = stage + r * 520;
        float a = 0.f;
#pragma unroll
        for (int itn = 0; itn < 16; itn++) {
            int n = lane + itn * 32;
            a += sv[n] * tanh_fast(sr[n] + sdec[n]);
        }
#pragma unroll
        for (int o = 16; o; o >>= 1) a += __shfl_down_sync(0xffffffffu, a, o);
        if (lane == 0) g_scores[bt * 64 + r] = a;
    }
}

// ---------------- softmax over TK per b -------------------------------------
__global__ void k_attn(float* __restrict__ out_attn) {
    __shared__ float red[32];
    int b = blockIdx.x, t = threadIdx.x;   // 1024 threads
    float s = g_scores[b * TKK + t];
    float m = s;
#pragma unroll
    for (int o = 16; o; o >>= 1) m = fmaxf(m, __shfl_xor_sync(0xffffffffu, m, o));
    if ((t & 31) == 0) red[t >> 5] = m;
    __syncthreads();
    if (t < 32) {
        float v = red[t];
#pragma unroll
        for (int o = 16; o; o >>= 1) v = fmaxf(v, __shfl_xor_sync(0xffffffffu, v, o));
        if (t == 0) red[0] = v;
    }
    __syncthreads();
    float mx = red[0];
    __syncthreads();
    float e = __expf(s - mx);
    float sm = e;
#pragma unroll
    for (int o = 16; o; o >>= 1) sm += __shfl_xor_sync(0xffffffffu, sm, o);
    if ((t & 31) == 0) red[t >> 5] = sm;
    __syncthreads();
    if (t < 32) {
        float v = red[t];
#pragma unroll
        for (int o = 16; o; o >>= 1) v += __shfl_xor_sync(0xffffffffu, v, o);
        if (t == 0) red[0] = v;
    }
    __syncthreads();
    out_attn[b * TKK + t] = e * (1.f / red[0]);
}

// ---------------- c_t partials ----------------------------------------------
__global__ void k_ct_part(const float* __restrict__ enc, const float* __restrict__ attn) {
    __shared__ float sa[64];
    int c = blockIdx.x, b = blockIdx.y, h = threadIdx.x;   // 512 threads
    if (h < 64) sa[h] = attn[b * TKK + c * 64 + h];
    __syncthreads();
    const float* e = enc + ((size_t)b * TKK + c * 64) * HH + h;
    float acc = 0.f;
#pragma unroll 8
    for (int t = 0; t < 64; t++) acc += sa[t] * e[(size_t)t * HH];
    g_cpart[((size_t)b * 16 + c) * HH + h] = acc;
}

__global__ void k_ct_fin(float* __restrict__ out_ct) {
    int b = blockIdx.x, h = threadIdx.x;   // 512
    float acc = 0.f;
#pragma unroll
    for (int c = 0; c < 16; c++) acc += g_cpart[((size_t)b * 16 + c) * HH + h];
    out_ct[b * HH + h] = acc;
    g_concatT[(HH + h) * BB + b] = acc;
}

// ---------------- logits via wmma, double buffered --------------------------
#define LG_SMEM (33280 + 20480)
__global__ __launch_bounds__(256) void k_logits_mma(const float* __restrict__ W,
                                                    const float* __restrict__ bias) {
    extern __shared__ char smraw[];
    __nv_bfloat16* As2 = (__nv_bfloat16*)smraw;                // [32][520]
    __nv_bfloat16* Ws  = (__nv_bfloat16*)(smraw + 33280);      // [2][128][40]
    float* stage = (float*)(smraw + 33280);                    // [32][136]

    int tid = threadIdx.x, warp = tid >> 5;
    int n0 = blockIdx.x * 128;
    for (int idx = tid; idx < BB * HH; idx += 256) {
        int r = idx >> 9, k = idx & 511;
        As2[r * 520 + k] = __float2bfloat16(g_out1[idx]);
    }

    wmma::fragment<wmma::accumulator, 16, 16, 16, float> acc[2];
    wmma::fill_fragment(acc[0], 0.f);
    wmma::fill_fragment(acc[1], 0.f);

    int lrow = tid >> 3, lq = tid & 7;
    float4 wreg[4];
#pragma unroll
    for (int p = 0; p < 4; p++) {
        int n = n0 + p * 32 + lrow;
        wreg[p] = (n < VOCAB) ? *(const float4*)(W + (size_t)n * HH + lq * 4)
                              : make_float4(0.f, 0.f, 0.f, 0.f);
    }
    for (int it = 0; it < 16; it++) {
        int cur = it & 1;
        __nv_bfloat16* wd = Ws + cur * (128 * 40);
#pragma unroll
        for (int p = 0; p < 4; p++) {
            __nv_bfloat16* d = wd + (p * 32 + lrow) * 40 + lq * 4;
            *(__nv_bfloat162*)d       = __floats2bfloat162_rn(wreg[p].x, wreg[p].y);
            *(__nv_bfloat162*)(d + 2) = __floats2bfloat162_rn(wreg[p].z, wreg[p].w);
        }
        if (it < 15) {
#pragma unroll
            for (int p = 0; p < 4; p++) {
                int n = n0 + p * 32 + lrow;
                wreg[p] = (n < VOCAB)
                    ? *(const float4*)(W + (size_t)n * HH + (it + 1) * 32 + lq * 4)
                    : make_float4(0.f, 0.f, 0.f, 0.f);
            }
        }
        __syncthreads();
#pragma unroll
        for (int kk = 0; kk < 32; kk += 16) {
            wmma::fragment<wmma::matrix_b, 16, 16, 16, __nv_bfloat16, wmma::col_major> bf;
            wmma::load_matrix_sync(bf, wd + (warp * 16) * 40 + kk, 40);
#pragma unroll
            for (int i = 0; i < 2; i++) {
                wmma::fragment<wmma::matrix_a, 16, 16, 16, __nv_bfloat16, wmma::row_major> af;
                wmma::load_matrix_sync(af, As2 + (i * 16) * 520 + it * 32 + kk, 520);
                wmma::mma_sync(acc[i], af, bf, acc[i]);
            }
        }
        __syncthreads();
    }
#pragma unroll
    for (int i = 0; i < 2; i++)
        wmma::store_matrix_sync(stage + (i * 16) * 136 + warp * 16, acc[i], 136,
                                wmma::mem_row_major);
    __syncthreads();
    for (int idx = tid; idx < 32 * 128; idx += 256) {
        int r = idx >> 7, c = idx & 127;
        int n = n0 + c;
        if (n < VOCAB)
            g_logits[(size_t)r * VOCAB + n] = stage[r * 136 + c] + bias[n];
    }
}

// ---------------- softmax over V per b --------------------------------------
__global__ void k_softmaxV(float* __restrict__ out_fd) {
    __shared__ float red[32];
    int b = blockIdx.x, tid = threadIdx.x;     // 512 threads
    const float* lg = g_logits + (size_t)b * VOCAB;
    float* dst = out_fd + (size_t)b * VOCAB;

    float m = -1e30f;
    for (int n = tid; n < VOCAB; n += 512) m = fmaxf(m, lg[n]);
#pragma unroll
    for (int o = 16; o; o >>= 1) m = fmaxf(m, __shfl_xor_sync(0xffffffffu, m, o));
    if ((tid & 31) == 0) red[tid >> 5] = m;
    __syncthreads();
    if (tid < 32) {
        float v = (tid < 16) ? red[tid] : -1e30f;
#pragma unroll
        for (int o = 16; o; o >>= 1) v = fmaxf(v, __shfl_xor_sync(0xffffffffu, v, o));
        if (tid == 0) red[0] = v;
    }
    __syncthreads();
    float mx = red[0];
    __syncthreads();
    float s = 0.f;
    for (int n = tid; n < VOCAB; n += 512) {
        float e = __expf(lg[n] - mx);
        dst[n] = e;
        s += e;
    }
#pragma unroll
    for (int o = 16; o; o >>= 1) s += __shfl_xor_sync(0xffffffffu, s, o);
    if ((tid & 31) == 0) red[tid >> 5] = s;
    __syncthreads();
    if (tid < 32) {
        float v = (tid < 16) ? red[tid] : 0.f;
#pragma unroll
        for (int o = 16; o; o >>= 1) v += __shfl_xor_sync(0xffffffffu, v, o);
        if (tid == 0) red[0] = v;
    }
    __syncthreads();
    float inv = 1.f / red[0];
    for (int n = tid; n < VOCAB; n += 512) dst[n] *= inv;
}

// ---------------- launcher ---------------------------------------------------
extern "C" void kernel_launch(void* const* d_in, const int* in_sizes, int n_in,
                              void* d_out, int out_size) {
    const int*   y      = (const int*)d_in[0];
    const float* s_t_1  = (const float*)d_in[2];
    const float* enc    = (const float*)d_in[3];
    const float* c_t_1  = (const float*)d_in[4];
    const float* cov    = (const float*)d_in[5];
    const float* emb    = (const float*)d_in[7];
    const float* xc_w   = (const float*)d_in[8];
    const float* xc_b   = (const float*)d_in[9];
    const float* Wh_w   = (const float*)d_in[10];
    const float* w_ih   = (const float*)d_in[11];
    const float* w_hh   = (const float*)d_in[12];
    const float* b_ih   = (const float*)d_in[13];
    const float* b_hh   = (const float*)d_in[14];
    const float* dp_w   = (const float*)d_in[15];
    const float* dp_b   = (const float*)d_in[16];
    const float* v_w    = (const float*)d_in[17];
    const float* out1_w = (const float*)d_in[18];
    const float* out1_b = (const float*)d_in[19];
    const float* out2_w = (const float*)d_in[20];
    const float* out2_b = (const float*)d_in[21];

    float* out      = (float*)d_out;
    float* out_fd   = out;
    float* out_st   = out_fd + (size_t)BB * VOCAB;
    float* out_ct   = out_st + BB * HH;
    float* out_attn = out_ct + BB * HH;
    float* out_cov  = out_attn + BB * TKK;

    float *p_xinT, *p_hT, *p_xT, *p_giT, *p_ghT, *p_hnewT, *p_dec, *p_concatT, *p_out1;
    cudaGetSymbolAddress((void**)&p_xinT,    g_xinT);
    cudaGetSymbolAddress((void**)&p_hT,      g_hT);
    cudaGetSymbolAddress((void**)&p_xT,      g_xT);
    cudaGetSymbolAddress((void**)&p_giT,     g_giT);
    cudaGetSymbolAddress((void**)&p_ghT,     g_ghT);
    cudaGetSymbolAddress((void**)&p_hnewT,   g_hnewT);
    cudaGetSymbolAddress((void**)&p_dec,     g_dec);
    cudaGetSymbolAddress((void**)&p_concatT, g_concatT);
    cudaGetSymbolAddress((void**)&p_out1,    g_out1);

    cudaFuncSetAttribute(k_fused_attn, cudaFuncAttributeMaxDynamicSharedMemorySize, FA_SMEM);
    cudaFuncSetAttribute(k_logits_mma, cudaFuncAttributeMaxDynamicSharedMemorySize, LG_SMEM);

    k_init_bias<<<544, 256>>>(xc_b, b_ih, b_hh, dp_b, out1_b);
    k_convert_wh<<<512, 256>>>(Wh_w);
    k_build_front<<<BB, 256>>>(y, c_t_1, s_t_1, emb);
    // x = xin @ xc_w^T        (N=256, K=768)
    k_bsplit<<<dim3(EE / 8, 4), 256>>>(p_xT, nullptr, p_xinT, xc_w, EE, HH + EE);
    // gh = h @ w_hh^T         (N=1536, K=512)
    k_bsplit<<<dim3(3 * HH / 8, 4), 256>>>(p_ghT, nullptr, p_hT, w_hh, 3 * HH, HH);
    // gi = x @ w_ih^T         (N=1536, K=256)
    k_bsplit<<<dim3(3 * HH / 8, 4), 256>>>(p_giT, nullptr, p_xT, w_ih, 3 * HH, EE);
    k_gru<<<HH / 8, 256>>>(out_st);
    // dec = h_new @ dp_w^T    (N=512, K=512)
    k_bsplit<<<dim3(HH / 8, 4), 256>>>(nullptr, p_dec, p_hnewT, dp_w, HH, HH);
    // fused attention scores
    k_fused_attn<<<M_ENC / 64, 512, FA_SMEM>>>(enc, v_w);
    k_attn<<<BB, 1024>>>(out_attn);
    k_ct_part<<<dim3(16, BB), 512>>>(enc, out_attn);
    k_ct_fin<<<BB, 512>>>(out_ct);
    // out1 = concat @ out1_w^T (N=512, K=1024)
    k_bsplit<<<dim3(HH / 8, 4), 256>>>(nullptr, p_out1, p_concatT, out1_w, HH, 2 * HH);
    k_logits_mma<<<(VOCAB + 127) / 128, 256, LG_SMEM>>>(out2_w, out2_b);
    k_softmaxV<<<BB, 512>>>(out_fd);
    cudaMemcpyAsync(out_cov, cov, (size_t)BB * TKK * sizeof(float),
                    cudaMemcpyDeviceToDevice, 0);
}